// round 7
// baseline (speedup 1.0000x reference)
#include <cuda_runtime.h>
#include <cuda_bf16.h>
#include <cstdint>

#define BATCH 8
#define NPOS 4096
#define CDIM 256

// Scratch: Q split-bf16 [b][n][64] (hi 0-31 | lo 32-63, pre-scaled by log2e),
// K plain bf16 [b][n][32], V channel-major bf16 [b][c][n].
__device__ __nv_bfloat16 g_q[(size_t)BATCH * NPOS * 64];
__device__ __nv_bfloat16 g_k[(size_t)BATCH * NPOS * 32];
__device__ __nv_bfloat16 g_v[(size_t)BATCH * CDIM * NPOS];

// ---------------- helpers ----------------
__device__ __forceinline__ uint32_t smem_u32(const void* p) {
    uint32_t a;
    asm("{ .reg .u64 t; cvta.to.shared.u64 t, %1; cvt.u32.u64 %0, t; }" : "=r"(a) : "l"(p));
    return a;
}
__device__ __forceinline__ float ex2f(float x) {
    float y; asm("ex2.approx.f32 %0, %1;" : "=f"(y) : "f"(x)); return y;
}
__device__ __forceinline__ void sts32(uint32_t a, uint32_t v) {
    asm volatile("st.shared.b32 [%0], %1;" :: "r"(a), "r"(v));
}
__device__ __forceinline__ void cp16(uint32_t dst, const void* src) {
    asm volatile("cp.async.cg.shared.global [%0], [%1], 16;" :: "r"(dst), "l"(src));
}
#define CP_COMMIT() asm volatile("cp.async.commit_group;" ::: "memory")
#define CP_WAIT(N)  asm volatile("cp.async.wait_group %0;" :: "n"(N) : "memory")

__device__ __forceinline__ void ldm_x4(uint32_t addr, uint32_t* r) {
    asm volatile("ldmatrix.sync.aligned.m8n8.x4.shared.b16 {%0,%1,%2,%3}, [%4];"
                 : "=r"(r[0]), "=r"(r[1]), "=r"(r[2]), "=r"(r[3]) : "r"(addr));
}
__device__ __forceinline__ void mma16816(float* c, const uint32_t* a, uint32_t b0, uint32_t b1) {
    asm volatile(
        "mma.sync.aligned.m16n8k16.row.col.f32.bf16.bf16.f32 "
        "{%0,%1,%2,%3}, {%4,%5,%6,%7}, {%8,%9}, {%0,%1,%2,%3};"
        : "+f"(c[0]), "+f"(c[1]), "+f"(c[2]), "+f"(c[3])
        : "r"(a[0]), "r"(a[1]), "r"(a[2]), "r"(a[3]), "r"(b0), "r"(b1));
}

// packed f32x2
__device__ __forceinline__ unsigned long long pack2(float lo, float hi) {
    unsigned long long r; asm("mov.b64 %0, {%1, %2};" : "=l"(r) : "f"(lo), "f"(hi)); return r;
}
__device__ __forceinline__ void unpack2(unsigned long long v, float& lo, float& hi) {
    asm("mov.b64 {%0, %1}, %2;" : "=f"(lo), "=f"(hi) : "l"(v));
}
__device__ __forceinline__ unsigned long long fma2(unsigned long long a, unsigned long long b,
                                                   unsigned long long c) {
    unsigned long long d; asm("fma.rn.f32x2 %0, %1, %2, %3;" : "=l"(d) : "l"(a), "l"(b), "l"(c));
    return d;
}

#define LOG2E 1.4426950408889634f

// ================= Kernel A: projections =================
// Block: 128n x 64o, 256 threads (tx = n-group of 8, ty = o-group of 4).
// W staged once in smem [c][o] (stride 68), x triple-buffered cp.async chunks of 16c.
#define PW_OFF  0        // floats: w[256*68]
#define PX_OFF  17408    // xs[3][16*128]
#define PSO_OFF 23552    // so[64*132]
#define PROJ_SMEM_BYTES (32000 * 4)

__global__ void __launch_bounds__(256) proj_kernel(
    const float* __restrict__ x,
    const float* __restrict__ Wq, const float* __restrict__ bq,
    const float* __restrict__ Wk, const float* __restrict__ bk,
    const float* __restrict__ Wv, const float* __restrict__ bv)
{
    extern __shared__ float psm[];
    float* w  = psm + PW_OFF;
    float* xs = psm + PX_OFF;
    float* so = psm + PSO_OFF;
    const uint32_t sbx = smem_u32(xs);

    const int b  = blockIdx.z;
    const int n0 = blockIdx.x * 128;
    const int ob = blockIdx.y * 64;
    const int tid = threadIdx.x;
    const int tx = tid & 15;
    const int ty = tid >> 4;

    // Stage W: w[c*68 + o], coalesced global reads
#pragma unroll 4
    for (int i = 0; i < 64; i++) {
        const int og = ob + i;
        const float* wrow;
        if (og < 32)      wrow = Wq + og * CDIM;
        else if (og < 64) wrow = Wk + (og - 32) * CDIM;
        else              wrow = Wv + (og - 64) * CDIM;
        w[tid * 68 + i] = wrow[tid];
    }

    const float* xb = x + (size_t)b * CDIM * NPOS + n0;

#define PROJ_LOAD(ci) do { \
    const int _buf = (ci) % 3; \
    _Pragma("unroll") \
    for (int e2 = tid; e2 < 512; e2 += 256) { \
        const int _cc = e2 >> 5, _nn = (e2 & 31) * 4; \
        cp16(sbx + _buf * 8192 + _cc * 512 + _nn * 4, \
             xb + (size_t)((ci) * 16 + _cc) * NPOS + _nn); \
    } CP_COMMIT(); } while (0)

    PROJ_LOAD(0);
    PROJ_LOAD(1);

    unsigned long long acc2[4][4];
#pragma unroll
    for (int j = 0; j < 4; j++)
#pragma unroll
        for (int p = 0; p < 4; p++) acc2[j][p] = pack2(0.f, 0.f);

    for (int i = 0; i < 16; i++) {
        if (i < 15) { CP_WAIT(1); } else { CP_WAIT(0); }
        __syncthreads();
        if (i + 2 < 16) PROJ_LOAD(i + 2);

        const float* xbuf = xs + (i % 3) * 2048;
#pragma unroll
        for (int cc = 0; cc < 16; cc++) {
            const float4 xa = *(const float4*)&xbuf[cc * 128 + tx * 8];
            const float4 xc = *(const float4*)&xbuf[cc * 128 + tx * 8 + 4];
            const float4 wv = *(const float4*)&w[(i * 16 + cc) * 68 + ty * 4];
            const unsigned long long x01 = pack2(xa.x, xa.y);
            const unsigned long long x23 = pack2(xa.z, xa.w);
            const unsigned long long x45 = pack2(xc.x, xc.y);
            const unsigned long long x67 = pack2(xc.z, xc.w);
            const float wa[4] = {wv.x, wv.y, wv.z, wv.w};
#pragma unroll
            for (int j = 0; j < 4; j++) {
                const unsigned long long w2 = pack2(wa[j], wa[j]);
                acc2[j][0] = fma2(w2, x01, acc2[j][0]);
                acc2[j][1] = fma2(w2, x23, acc2[j][1]);
                acc2[j][2] = fma2(w2, x45, acc2[j][2]);
                acc2[j][3] = fma2(w2, x67, acc2[j][3]);
            }
        }
        __syncthreads();
    }

    // bias + stage so[o][n]
    float bias[4];
#pragma unroll
    for (int j = 0; j < 4; j++) {
        const int og = ob + ty * 4 + j;
        bias[j] = (og < 32) ? bq[og] : (og < 64 ? bk[og - 32] : bv[og - 64]);
    }
#pragma unroll
    for (int j = 0; j < 4; j++) {
        float v0, v1;
#pragma unroll
        for (int p = 0; p < 4; p++) {
            unpack2(acc2[j][p], v0, v1);
            so[(ty * 4 + j) * 132 + tx * 8 + p * 2]     = v0 + bias[j];
            so[(ty * 4 + j) * 132 + tx * 8 + p * 2 + 1] = v1 + bias[j];
        }
    }
    __syncthreads();

    if (ob == 0) {
        const int n = tid >> 1;
        if ((tid & 1) == 0) {
            // Q row n: o 0..31, split hi/lo, scale log2e
            uint32_t hv[16], lv[16];
#pragma unroll
            for (int e = 0; e < 32; e += 2) {
                const float t0 = so[e * 132 + n] * LOG2E;
                const float t1 = so[(e + 1) * 132 + n] * LOG2E;
                const __nv_bfloat16 h0 = __float2bfloat16_rn(t0);
                const __nv_bfloat16 h1 = __float2bfloat16_rn(t1);
                __nv_bfloat162 hh; hh.x = h0; hh.y = h1;
                hv[e >> 1] = *(const uint32_t*)&hh;
                const __nv_bfloat162 l2 =
                    __floats2bfloat162_rn(t0 - __bfloat162float(h0), t1 - __bfloat162float(h1));
                lv[e >> 1] = *(const uint32_t*)&l2;
            }
            char* row = (char*)(g_q + (((size_t)b << 12) + n0 + n) * 64);
#pragma unroll
            for (int q4 = 0; q4 < 4; q4++) {
                *(uint4*)(row + q4 * 16) =
                    make_uint4(hv[q4 * 4], hv[q4 * 4 + 1], hv[q4 * 4 + 2], hv[q4 * 4 + 3]);
                *(uint4*)(row + 64 + q4 * 16) =
                    make_uint4(lv[q4 * 4], lv[q4 * 4 + 1], lv[q4 * 4 + 2], lv[q4 * 4 + 3]);
            }
        } else {
            // K row n: o 32..63
            uint32_t kv[16];
#pragma unroll
            for (int e = 0; e < 32; e += 2) {
                const __nv_bfloat162 hh =
                    __floats2bfloat162_rn(so[(32 + e) * 132 + n], so[(33 + e) * 132 + n]);
                kv[e >> 1] = *(const uint32_t*)&hh;
            }
            char* row = (char*)(g_k + (((size_t)b << 12) + n0 + n) * 32);
#pragma unroll
            for (int q4 = 0; q4 < 4; q4++)
                *(uint4*)(row + q4 * 16) =
                    make_uint4(kv[q4 * 4], kv[q4 * 4 + 1], kv[q4 * 4 + 2], kv[q4 * 4 + 3]);
        }
    } else {
        // V: channel-major. thread -> channel c = tid>>2, n-quarter = (tid&3)*32
        const int c = tid >> 2;
        const int qn = (tid & 3) * 32;
        uint32_t vv[16];
#pragma unroll
        for (int e = 0; e < 32; e += 2) {
            const __nv_bfloat162 t2 =
                __floats2bfloat162_rn(so[c * 132 + qn + e], so[c * 132 + qn + e + 1]);
            vv[e >> 1] = *(const uint32_t*)&t2;
        }
        char* dst = (char*)(g_v + (((size_t)(b * CDIM + ob - 64 + c)) << 12) + n0 + qn);
#pragma unroll
        for (int q4 = 0; q4 < 4; q4++)
            *(uint4*)(dst + q4 * 16) =
                make_uint4(vv[q4 * 4], vv[q4 * 4 + 1], vv[q4 * 4 + 2], vv[q4 * 4 + 3]);
    }
}

// ================= Kernel B: HMMA flash attention, 1 barrier/tile =================
// smem: Q@0 (128x144), K@18432 (4x 64x80), P@38912 (2x 128x144),
// rowsum@75776 (128x2 f32), V@76800 (4x 256x144). OST epilogue reuses V.
#define QS_OFF 0
#define KS_OFF 18432
#define K_STR  5120
#define PS_OFF 38912
#define P_STR  18432
#define RS_OFF 75776
#define VS_OFF 76800
#define V_STR  36864
#define SMEM_BYTES 224256

__global__ void __launch_bounds__(512, 1) attn_kernel(
    const float* __restrict__ x,
    const float* __restrict__ gamma,
    float* __restrict__ out)
{
    extern __shared__ char smc[];
    const uint32_t sb = smem_u32(smc);
    const int tid = threadIdx.x;
    const int w = tid >> 5, lane = tid & 31;
    const int lg = lane >> 2, ll = lane & 3;
    const int b = blockIdx.y, m0 = blockIdx.x * 128;

    const int s_mb = (w >> 1) * 16, s_nb = (w & 1) * 32;
    const int p_mb = (w >> 2) * 32, p_cb = (w & 3) * 64;

    const uint32_t a_off   = (lane & 15) * 144 + ((lane >> 4) << 4);
    const uint32_t b_off_v = ((lane & 7) + ((lane >> 4) << 3)) * 144 + (((lane >> 3) & 1) << 4);
    const uint32_t b_off_k = ((lane & 7) + ((lane >> 4) << 3)) * 80  + (((lane >> 3) & 1) << 4);

    const char* gq = (const char*)g_q + ((size_t)(b << 12) + m0) * 128;
    const char* gk = (const char*)g_k + ((size_t)b << 18);
    const char* gv = (const char*)g_v + (size_t)b * CDIM * 8192;

#define LOAD_KV(t2) do { \
    const int _sl = (t2) & 3; \
    if (tid < 256) \
        cp16(sb + KS_OFF + _sl * K_STR + (tid >> 2) * 80 + (tid & 3) * 16, \
             gk + (size_t)(t2) * 4096 + tid * 16); \
    _Pragma("unroll") \
    for (int _i = 0; _i < 4; _i++) { \
        const int _e = tid + _i * 512, _c = _e >> 3, _j = _e & 7; \
        cp16(sb + VS_OFF + _sl * V_STR + _c * 144 + _j * 16, \
             gv + (size_t)_c * 8192 + (size_t)(t2) * 128 + _j * 16); \
    } CP_COMMIT(); } while (0)

    // Prologue: G0 = Q + K0 + V0; G1 = K1 + V1
#pragma unroll
    for (int i = 0; i < 2; i++) {
        const int e = tid + i * 512;
        cp16(sb + QS_OFF + (e >> 3) * 144 + (e & 7) * 16, gq + e * 16);
    }
    if (tid < 256)
        cp16(sb + KS_OFF + (tid >> 2) * 80 + (tid & 3) * 16, gk + tid * 16);
#pragma unroll
    for (int i = 0; i < 4; i++) {
        const int e = tid + i * 512, c = e >> 3, jj = e & 7;
        cp16(sb + VS_OFF + c * 144 + jj * 16, gv + (size_t)c * 8192 + jj * 16);
    }
    CP_COMMIT();
    LOAD_KV(1);
    CP_WAIT(0);
    __syncthreads();

    float of[2][8][4];
#pragma unroll
    for (int mt = 0; mt < 2; mt++)
#pragma unroll
        for (int nf = 0; nf < 8; nf++)
#pragma unroll
            for (int r = 0; r < 4; r++) of[mt][nf][r] = 0.0f;
    float rsA = 0.0f, rsB = 0.0f;

    // S(tile) -> softmax -> P store into buffer (tile)&1
#define S_TILE(TILE) do { \
    const uint32_t kbt = sb + KS_OFF + ((TILE) & 3) * K_STR; \
    uint32_t bfr[2][2][4]; \
    _Pragma("unroll") \
    for (int ks = 0; ks < 2; ks++) \
        _Pragma("unroll") \
        for (int np = 0; np < 2; np++) \
            ldm_x4(kbt + (uint32_t)(s_nb + np * 16) * 80 + b_off_k + ks * 32, bfr[ks][np]); \
    float sf[4][4]; \
    _Pragma("unroll") \
    for (int nf = 0; nf < 4; nf++) \
        _Pragma("unroll") \
        for (int r = 0; r < 4; r++) sf[nf][r] = 0.0f; \
    _Pragma("unroll") \
    for (int pass = 0; pass < 2; pass++) { \
        _Pragma("unroll") \
        for (int ks = 0; ks < 2; ks++) { \
            uint32_t a[4]; \
            ldm_x4(sb + QS_OFF + (uint32_t)s_mb * 144 + a_off + pass * 64 + ks * 32, a); \
            _Pragma("unroll") \
            for (int nf = 0; nf < 4; nf++) \
                mma16816(sf[nf], a, bfr[ks][nf >> 1][(nf & 1) * 2], \
                         bfr[ks][nf >> 1][(nf & 1) * 2 + 1]); \
        } \
    } \
    const uint32_t pr0 = sb + PS_OFF + ((TILE) & 1) * P_STR + (s_mb + lg) * 144; \
    _Pragma("unroll") \
    for (int nf = 0; nf < 4; nf++) { \
        const float p0 = ex2f(sf[nf][0]), p1 = ex2f(sf[nf][1]); \
        const float p2 = ex2f(sf[nf][2]), p3 = ex2f(sf[nf][3]); \
        const __nv_bfloat162 t01 = __floats2bfloat162_rn(p0, p1); \
        const __nv_bfloat162 t23 = __floats2bfloat162_rn(p2, p3); \
        const float2 f01 = __bfloat1622float2(t01); \
        const float2 f23 = __bfloat1622float2(t23); \
        rsA += f01.x + f01.y; \
        rsB += f23.x + f23.y; \
        const int nb = (s_nb + nf * 8 + ll * 2) * 2; \
        sts32(pr0 + nb, *(const uint32_t*)&t01); \
        sts32(pr0 + 8 * 144 + nb, *(const uint32_t*)&t23); \
    } } while (0)

    // S(0) -> P buffer 0 (published by sync at iteration 0)
    S_TILE(0);

    for (int kt = 0; kt < 64; kt++) {
        if (kt + 2 < 64) LOAD_KV(kt + 2);
        if (kt < 62) { CP_WAIT(1); } else { CP_WAIT(0); }
        __syncthreads();  // publishes P(kt); K/V(kt+1) ready; PV(kt-1) done by all

        if (kt < 63) S_TILE(kt + 1);

        // PV(kt): O += P(kt).V(kt)^T
        const uint32_t pt = sb + PS_OFF + (kt & 1) * P_STR;
        const uint32_t vt = sb + VS_OFF + (kt & 3) * V_STR;
#pragma unroll
        for (int ks = 0; ks < 4; ks++) {
            const int kb = ks * 32;
            uint32_t pa[2][4];
            ldm_x4(pt + (uint32_t)p_mb * 144 + a_off + kb, pa[0]);
            ldm_x4(pt + (uint32_t)(p_mb + 16) * 144 + a_off + kb, pa[1]);
            uint32_t vb[4][4];
#pragma unroll
            for (int np = 0; np < 4; np++)
                ldm_x4(vt + (uint32_t)(p_cb + np * 16) * 144 + b_off_v + kb, vb[np]);
#pragma unroll
            for (int nf = 0; nf < 8; nf++) {
                const uint32_t b0 = vb[nf >> 1][(nf & 1) * 2];
                const uint32_t b1 = vb[nf >> 1][(nf & 1) * 2 + 1];
                mma16816(of[0][nf], pa[0], b0, b1);
                mma16816(of[1][nf], pa[1], b0, b1);
            }
        }
    }

    // ---- epilogue ----
    rsA += __shfl_xor_sync(0xffffffffu, rsA, 1);
    rsA += __shfl_xor_sync(0xffffffffu, rsA, 2);
    rsB += __shfl_xor_sync(0xffffffffu, rsB, 1);
    rsB += __shfl_xor_sync(0xffffffffu, rsB, 2);
    float* rowarr = (float*)(smc + RS_OFF);
    if (ll == 0) {
        rowarr[(s_mb + lg) * 2 + (w & 1)] = rsA;
        rowarr[(s_mb + 8 + lg) * 2 + (w & 1)] = rsB;
    }
    __syncthreads();

    const float gm = gamma[0];
    float inv[4];
#pragma unroll
    for (int mt = 0; mt < 2; mt++)
#pragma unroll
        for (int h = 0; h < 2; h++) {
            const int r = p_mb + mt * 16 + h * 8 + lg;
            inv[mt * 2 + h] = gm / (rowarr[2 * r] + rowarr[2 * r + 1]);
        }

    float* ost = (float*)(smc + VS_OFF);
#pragma unroll 1
    for (int chunk = 0; chunk < 2; chunk++) {
        if (((w & 3) >> 1) == chunk) {
#pragma unroll
            for (int mt = 0; mt < 2; mt++)
#pragma unroll
                for (int nf = 0; nf < 8; nf++) {
                    const int cl = (p_cb - chunk * 128) + nf * 8 + ll * 2;
                    const int m = p_mb + mt * 16 + lg;
                    ost[cl * 132 + m]           = of[mt][nf][0] * inv[mt * 2];
                    ost[(cl + 1) * 132 + m]     = of[mt][nf][1] * inv[mt * 2];
                    ost[cl * 132 + m + 8]       = of[mt][nf][2] * inv[mt * 2 + 1];
                    ost[(cl + 1) * 132 + m + 8] = of[mt][nf][3] * inv[mt * 2 + 1];
                }
        }
        __syncthreads();
        const int m = tid & 127, cb = tid >> 7;
#pragma unroll 4
        for (int cc = 0; cc < 32; cc++) {
            const int cl = cc * 4 + cb;
            const int c = chunk * 128 + cl;
            const size_t off = ((size_t)b * CDIM + c) * NPOS + m0 + m;
            out[off] = ost[cl * 132 + m] + x[off];
        }
        __syncthreads();
    }
}

// ================= launch =================
extern "C" void kernel_launch(void* const* d_in, const int* in_sizes, int n_in,
                              void* d_out, int out_size)
{
    const float* x     = (const float*)d_in[0];
    const float* Wq    = (const float*)d_in[1];
    const float* bq    = (const float*)d_in[2];
    const float* Wk    = (const float*)d_in[3];
    const float* bk    = (const float*)d_in[4];
    const float* Wv    = (const float*)d_in[5];
    const float* bv    = (const float*)d_in[6];
    const float* gamma = (const float*)d_in[7];
    float* out = (float*)d_out;

    cudaFuncSetAttribute(proj_kernel, cudaFuncAttributeMaxDynamicSharedMemorySize,
                         PROJ_SMEM_BYTES);
    proj_kernel<<<dim3(NPOS / 128, 5, BATCH), 256, PROJ_SMEM_BYTES>>>(
        x, Wq, bq, Wk, bk, Wv, bv);

    cudaFuncSetAttribute(attn_kernel, cudaFuncAttributeMaxDynamicSharedMemorySize,
                         SMEM_BYTES);
    attn_kernel<<<dim3(NPOS / 128, BATCH), 512, SMEM_BYTES>>>(x, gamma, out);
}

// round 8
// speedup vs baseline: 1.1926x; 1.1926x over previous
#include <cuda_runtime.h>
#include <cuda_bf16.h>
#include <cstdint>

#define BATCH 8
#define NPOS 4096
#define CDIM 256

// Scratch: Q bf16 [b][n][32] (pre-scaled by log2e), K bf16 [b][n][32],
// V channel-major bf16 [b][c][n].
__device__ __nv_bfloat16 g_q[(size_t)BATCH * NPOS * 32];
__device__ __nv_bfloat16 g_k[(size_t)BATCH * NPOS * 32];
__device__ __nv_bfloat16 g_v[(size_t)BATCH * CDIM * NPOS];

// ---------------- helpers ----------------
__device__ __forceinline__ uint32_t smem_u32(const void* p) {
    uint32_t a;
    asm("{ .reg .u64 t; cvta.to.shared.u64 t, %1; cvt.u32.u64 %0, t; }" : "=r"(a) : "l"(p));
    return a;
}
__device__ __forceinline__ float ex2f(float x) {
    float y; asm("ex2.approx.f32 %0, %1;" : "=f"(y) : "f"(x)); return y;
}
__device__ __forceinline__ void sts32(uint32_t a, uint32_t v) {
    asm volatile("st.shared.b32 [%0], %1;" :: "r"(a), "r"(v));
}
__device__ __forceinline__ void cp16(uint32_t dst, const void* src) {
    asm volatile("cp.async.cg.shared.global [%0], [%1], 16;" :: "r"(dst), "l"(src));
}
#define CP_COMMIT() asm volatile("cp.async.commit_group;" ::: "memory")
#define CP_WAIT(N)  asm volatile("cp.async.wait_group %0;" :: "n"(N) : "memory")

__device__ __forceinline__ void ldm_x4(uint32_t addr, uint32_t* r) {
    asm volatile("ldmatrix.sync.aligned.m8n8.x4.shared.b16 {%0,%1,%2,%3}, [%4];"
                 : "=r"(r[0]), "=r"(r[1]), "=r"(r[2]), "=r"(r[3]) : "r"(addr));
}
__device__ __forceinline__ void mma16816(float* c, const uint32_t* a, uint32_t b0, uint32_t b1) {
    asm volatile(
        "mma.sync.aligned.m16n8k16.row.col.f32.bf16.bf16.f32 "
        "{%0,%1,%2,%3}, {%4,%5,%6,%7}, {%8,%9}, {%0,%1,%2,%3};"
        : "+f"(c[0]), "+f"(c[1]), "+f"(c[2]), "+f"(c[3])
        : "r"(a[0]), "r"(a[1]), "r"(a[2]), "r"(a[3]), "r"(b0), "r"(b1));
}

// packed f32x2
__device__ __forceinline__ unsigned long long pack2(float lo, float hi) {
    unsigned long long r; asm("mov.b64 %0, {%1, %2};" : "=l"(r) : "f"(lo), "f"(hi)); return r;
}
__device__ __forceinline__ void unpack2(unsigned long long v, float& lo, float& hi) {
    asm("mov.b64 {%0, %1}, %2;" : "=f"(lo), "=f"(hi) : "l"(v));
}
__device__ __forceinline__ unsigned long long fma2(unsigned long long a, unsigned long long b,
                                                   unsigned long long c) {
    unsigned long long d; asm("fma.rn.f32x2 %0, %1, %2, %3;" : "=l"(d) : "l"(a), "l"(b), "l"(c));
    return d;
}

#define LOG2E 1.4426950408889634f

// ================= Kernel A: projections (R6 version, plain-Q store) =================
__global__ __launch_bounds__(256) void proj_kernel(
    const float* __restrict__ x,
    const float* __restrict__ Wq, const float* __restrict__ bq,
    const float* __restrict__ Wk, const float* __restrict__ bk,
    const float* __restrict__ Wv, const float* __restrict__ bv)
{
    __shared__ float xs[16][64];
    __shared__ float ws[16][64];
    __shared__ float so[64][68];

    const int b  = blockIdx.z;
    const int n0 = blockIdx.x * 64;
    const int ob = blockIdx.y * 64;
    const int tid = threadIdx.x;
    const int tx = tid & 15;
    const int ty = tid >> 4;

    unsigned long long a2[4][2];
#pragma unroll
    for (int i = 0; i < 4; i++) { a2[i][0] = pack2(0.f, 0.f); a2[i][1] = pack2(0.f, 0.f); }

    const float* xb = x + (size_t)b * CDIM * NPOS;

    for (int c0 = 0; c0 < CDIM; c0 += 16) {
        __syncthreads();
        {
            const int cc = tid >> 4;
            const int nn = (tid & 15) * 4;
            *(float4*)&xs[cc][nn] = *(const float4*)(xb + (size_t)(c0 + cc) * NPOS + n0 + nn);
        }
        for (int e = tid; e < 1024; e += 256) {
            const int o  = e >> 4;
            const int cc = e & 15;
            const int og = ob + o;
            const float* wrow;
            if (og < 32)      wrow = Wq + og * CDIM;
            else if (og < 64) wrow = Wk + (og - 32) * CDIM;
            else              wrow = Wv + (og - 64) * CDIM;
            ws[cc][o] = wrow[c0 + cc];
        }
        __syncthreads();
#pragma unroll
        for (int cc = 0; cc < 16; cc++) {
            const float4 wv = *(const float4*)&ws[cc][ty * 4];
            const float4 xv = *(const float4*)&xs[cc][tx * 4];
            const unsigned long long x01 = pack2(xv.x, xv.y);
            const unsigned long long x23 = pack2(xv.z, xv.w);
            const float wa[4] = {wv.x, wv.y, wv.z, wv.w};
#pragma unroll
            for (int i = 0; i < 4; i++) {
                const unsigned long long w2 = pack2(wa[i], wa[i]);
                a2[i][0] = fma2(w2, x01, a2[i][0]);
                a2[i][1] = fma2(w2, x23, a2[i][1]);
            }
        }
    }

    float acc[4][4];
#pragma unroll
    for (int i = 0; i < 4; i++) {
        unpack2(a2[i][0], acc[i][0], acc[i][1]);
        unpack2(a2[i][1], acc[i][2], acc[i][3]);
    }

    const int og0 = ob + ty * 4;
    float bias[4];
#pragma unroll
    for (int i = 0; i < 4; i++) {
        const int og = og0 + i;
        bias[i] = (og < 32) ? bq[og] : (og < 64 ? bk[og - 32] : bv[og - 64]);
    }

    __syncthreads();
#pragma unroll
    for (int i = 0; i < 4; i++)
#pragma unroll
        for (int j = 0; j < 4; j++)
            so[ty * 4 + i][tx * 4 + j] = acc[i][j] + bias[i];
    __syncthreads();

    const int nn = tid >> 2;
    const int j  = tid & 3;
    if (ob == 0) {
        // Q row nn (o = j*8..j*8+7), scaled by log2e, plain bf16
        {
            uint32_t hv[4];
#pragma unroll
            for (int e = 0; e < 8; e += 2) {
                const __nv_bfloat162 hh = __floats2bfloat162_rn(
                    so[j * 8 + e][nn] * LOG2E, so[j * 8 + e + 1][nn] * LOG2E);
                hv[e >> 1] = *(const uint32_t*)&hh;
            }
            char* row = (char*)(g_q + (((size_t)b << 12) + n0 + nn) * 32);
            *(uint4*)(row + j * 16) = make_uint4(hv[0], hv[1], hv[2], hv[3]);
        }
        // K row nn (o 32..63)
        {
            uint32_t kv[4];
#pragma unroll
            for (int e = 0; e < 8; e += 2) {
                const __nv_bfloat162 hh =
                    __floats2bfloat162_rn(so[32 + j * 8 + e][nn], so[32 + j * 8 + e + 1][nn]);
                kv[e >> 1] = *(const uint32_t*)&hh;
            }
            char* row = (char*)(g_k + (((size_t)b << 12) + n0 + nn) * 32);
            *(uint4*)(row + j * 16) = make_uint4(kv[0], kv[1], kv[2], kv[3]);
        }
    } else {
        // V: channel-major rows
        uint32_t wv[8];
#pragma unroll
        for (int e = 0; e < 16; e += 2) {
            const __nv_bfloat162 t2 =
                __floats2bfloat162_rn(so[nn][j * 16 + e], so[nn][j * 16 + e + 1]);
            wv[e >> 1] = *(const uint32_t*)&t2;
        }
        const int c = ob - 64 + nn;
        char* dst = (char*)(g_v + (((size_t)(b * CDIM + c)) << 12) + n0) + j * 32;
        *(uint4*)dst        = make_uint4(wv[0], wv[1], wv[2], wv[3]);
        *(uint4*)(dst + 16) = make_uint4(wv[4], wv[5], wv[6], wv[7]);
    }
}

// ================= Kernel B: HMMA flash attention, softmax folded into PV =================
// smem: Q@0 (128x80), K@10240 (4x 64x80), P@30720 (2x 128x144),
// rowsum@67584 (128x2 f32), V@68608 (4x 256x144). OST epilogue reuses V.
#define QS_OFF 0
#define KS_OFF 10240
#define K_STR  5120
#define PS_OFF 30720
#define P_STR  18432
#define RS_OFF 67584
#define VS_OFF 68608
#define V_STR  36864
#define SMEM_BYTES 216064

__global__ void __launch_bounds__(512, 1) attn_kernel(
    const float* __restrict__ x,
    const float* __restrict__ gamma,
    float* __restrict__ out)
{
    extern __shared__ char smc[];
    const uint32_t sb = smem_u32(smc);
    const int tid = threadIdx.x;
    const int w = tid >> 5, lane = tid & 31;
    const int lg = lane >> 2, ll = lane & 3;
    const int b = blockIdx.y, m0 = blockIdx.x * 128;

    const int s_mb = (w >> 1) * 16, s_nb = (w & 1) * 32;
    const int p_mb = (w >> 2) * 32, p_cb = (w & 3) * 64;

    const uint32_t a_off144 = (lane & 15) * 144 + ((lane >> 4) << 4);
    const uint32_t a_off80  = (lane & 15) * 80  + ((lane >> 4) << 4);
    const uint32_t b_off_v  = ((lane & 7) + ((lane >> 4) << 3)) * 144 + (((lane >> 3) & 1) << 4);
    const uint32_t b_off_k  = ((lane & 7) + ((lane >> 4) << 3)) * 80  + (((lane >> 3) & 1) << 4);

    const char* gq = (const char*)g_q + ((size_t)(b << 12) + m0) * 64;
    const char* gk = (const char*)g_k + ((size_t)b << 18);
    const char* gv = (const char*)g_v + (size_t)b * CDIM * 8192;

#define LOAD_KV(t2) do { \
    const int _sl = (t2) & 3; \
    if (tid < 256) \
        cp16(sb + KS_OFF + _sl * K_STR + (tid >> 2) * 80 + (tid & 3) * 16, \
             gk + (size_t)(t2) * 4096 + tid * 16); \
    _Pragma("unroll") \
    for (int _i = 0; _i < 4; _i++) { \
        const int _e = tid + _i * 512, _c = _e >> 3, _j = _e & 7; \
        cp16(sb + VS_OFF + _sl * V_STR + _c * 144 + _j * 16, \
             gv + (size_t)_c * 8192 + (size_t)(t2) * 128 + _j * 16); \
    } CP_COMMIT(); } while (0)

    // Prologue: G0 = Q + K0 + V0; G1 = K1 + V1
    cp16(sb + QS_OFF + (tid >> 2) * 80 + (tid & 3) * 16, gq + tid * 16);
    if (tid < 256)
        cp16(sb + KS_OFF + (tid >> 2) * 80 + (tid & 3) * 16, gk + tid * 16);
#pragma unroll
    for (int i = 0; i < 4; i++) {
        const int e = tid + i * 512, c = e >> 3, jj = e & 7;
        cp16(sb + VS_OFF + c * 144 + jj * 16, gv + (size_t)c * 8192 + jj * 16);
    }
    CP_COMMIT();
    LOAD_KV(1);
    CP_WAIT(0);
    __syncthreads();

    float of[2][8][4];
#pragma unroll
    for (int mt = 0; mt < 2; mt++)
#pragma unroll
        for (int nf = 0; nf < 8; nf++)
#pragma unroll
            for (int r = 0; r < 4; r++) of[mt][nf][r] = 0.0f;
    float rsA = 0.0f, rsB = 0.0f;

    // S(tile) compute into sf (8 MMA)
#define S_COMPUTE(TILE, sf) do { \
    const uint32_t kbt = sb + KS_OFF + ((TILE) & 3) * K_STR; \
    uint32_t bfr[2][2][4]; \
    _Pragma("unroll") \
    for (int ks = 0; ks < 2; ks++) \
        _Pragma("unroll") \
        for (int np = 0; np < 2; np++) \
            ldm_x4(kbt + (uint32_t)(s_nb + np * 16) * 80 + b_off_k + ks * 32, bfr[ks][np]); \
    _Pragma("unroll") \
    for (int ks = 0; ks < 2; ks++) { \
        uint32_t a[4]; \
        ldm_x4(sb + QS_OFF + (uint32_t)s_mb * 80 + a_off80 + ks * 32, a); \
        _Pragma("unroll") \
        for (int nf = 0; nf < 4; nf++) \
            mma16816(sf[nf], a, bfr[ks][nf >> 1][(nf & 1) * 2], \
                     bfr[ks][nf >> 1][(nf & 1) * 2 + 1]); \
    } } while (0)

    // one softmax quarter: frag NF of sf -> P buffer (TILE)&1
#define SOFTMAX_Q(TILE, NF, sf) do { \
    const float p0 = ex2f(sf[NF][0]), p1 = ex2f(sf[NF][1]); \
    const float p2 = ex2f(sf[NF][2]), p3 = ex2f(sf[NF][3]); \
    const __nv_bfloat162 t01 = __floats2bfloat162_rn(p0, p1); \
    const __nv_bfloat162 t23 = __floats2bfloat162_rn(p2, p3); \
    const float2 f01 = __bfloat1622float2(t01); \
    const float2 f23 = __bfloat1622float2(t23); \
    rsA += f01.x + f01.y; \
    rsB += f23.x + f23.y; \
    const uint32_t pr0 = sb + PS_OFF + ((TILE) & 1) * P_STR + (s_mb + lg) * 144; \
    const int nb = (s_nb + (NF) * 8 + ll * 2) * 2; \
    sts32(pr0 + nb, *(const uint32_t*)&t01); \
    sts32(pr0 + 8 * 144 + nb, *(const uint32_t*)&t23); } while (0)

    // S(0) + softmax -> P buffer 0 (published by sync at iteration 0)
    {
        float sf[4][4];
#pragma unroll
        for (int nf = 0; nf < 4; nf++)
#pragma unroll
            for (int r = 0; r < 4; r++) sf[nf][r] = 0.0f;
        S_COMPUTE(0, sf);
#pragma unroll
        for (int nf = 0; nf < 4; nf++) SOFTMAX_Q(0, nf, sf);
    }

    for (int kt = 0; kt < 64; kt++) {
        if (kt + 2 < 64) LOAD_KV(kt + 2);
        if (kt < 62) { CP_WAIT(1); } else { CP_WAIT(0); }
        __syncthreads();  // publishes P(kt); K/V(kt+1) ready; PV(kt-1) done by all

        const bool doS = (kt < 63);
        float sf[4][4];
#pragma unroll
        for (int nf = 0; nf < 4; nf++)
#pragma unroll
            for (int r = 0; r < 4; r++) sf[nf][r] = 0.0f;
        if (doS) S_COMPUTE(kt + 1, sf);

        // PV(kt) with softmax(kt+1) quarters interleaved per ks-block
        const uint32_t pt = sb + PS_OFF + (kt & 1) * P_STR;
        const uint32_t vt = sb + VS_OFF + (kt & 3) * V_STR;
#pragma unroll
        for (int ks = 0; ks < 4; ks++) {
            const int kb = ks * 32;
            uint32_t pa[2][4];
            ldm_x4(pt + (uint32_t)p_mb * 144 + a_off144 + kb, pa[0]);
            ldm_x4(pt + (uint32_t)(p_mb + 16) * 144 + a_off144 + kb, pa[1]);
            uint32_t vb[4][4];
#pragma unroll
            for (int np = 0; np < 4; np++)
                ldm_x4(vt + (uint32_t)(p_cb + np * 16) * 144 + b_off_v + kb, vb[np]);
#pragma unroll
            for (int nf = 0; nf < 8; nf++) {
                const uint32_t b0 = vb[nf >> 1][(nf & 1) * 2];
                const uint32_t b1 = vb[nf >> 1][(nf & 1) * 2 + 1];
                mma16816(of[0][nf], pa[0], b0, b1);
                mma16816(of[1][nf], pa[1], b0, b1);
            }
            if (doS) SOFTMAX_Q(kt + 1, ks, sf);
        }
    }

    // ---- epilogue ----
    rsA += __shfl_xor_sync(0xffffffffu, rsA, 1);
    rsA += __shfl_xor_sync(0xffffffffu, rsA, 2);
    rsB += __shfl_xor_sync(0xffffffffu, rsB, 1);
    rsB += __shfl_xor_sync(0xffffffffu, rsB, 2);
    float* rowarr = (float*)(smc + RS_OFF);
    if (ll == 0) {
        rowarr[(s_mb + lg) * 2 + (w & 1)] = rsA;
        rowarr[(s_mb + 8 + lg) * 2 + (w & 1)] = rsB;
    }
    __syncthreads();

    const float gm = gamma[0];
    float inv[4];
#pragma unroll
    for (int mt = 0; mt < 2; mt++)
#pragma unroll
        for (int h = 0; h < 2; h++) {
            const int r = p_mb + mt * 16 + h * 8 + lg;
            inv[mt * 2 + h] = gm / (rowarr[2 * r] + rowarr[2 * r + 1]);
        }

    float* ost = (float*)(smc + VS_OFF);
#pragma unroll 1
    for (int chunk = 0; chunk < 2; chunk++) {
        if (((w & 3) >> 1) == chunk) {
#pragma unroll
            for (int mt = 0; mt < 2; mt++)
#pragma unroll
                for (int nf = 0; nf < 8; nf++) {
                    const int cl = (p_cb - chunk * 128) + nf * 8 + ll * 2;
                    const int m = p_mb + mt * 16 + lg;
                    ost[cl * 132 + m]           = of[mt][nf][0] * inv[mt * 2];
                    ost[(cl + 1) * 132 + m]     = of[mt][nf][1] * inv[mt * 2];
                    ost[cl * 132 + m + 8]       = of[mt][nf][2] * inv[mt * 2 + 1];
                    ost[(cl + 1) * 132 + m + 8] = of[mt][nf][3] * inv[mt * 2 + 1];
                }
        }
        __syncthreads();
        const int m = tid & 127, cb = tid >> 7;
#pragma unroll 4
        for (int cc = 0; cc < 32; cc++) {
            const int cl = cc * 4 + cb;
            const int c = chunk * 128 + cl;
            const size_t off = ((size_t)b * CDIM + c) * NPOS + m0 + m;
            out[off] = ost[cl * 132 + m] + x[off];
        }
        __syncthreads();
    }
}

// ================= launch =================
extern "C" void kernel_launch(void* const* d_in, const int* in_sizes, int n_in,
                              void* d_out, int out_size)
{
    const float* x     = (const float*)d_in[0];
    const float* Wq    = (const float*)d_in[1];
    const float* bq    = (const float*)d_in[2];
    const float* Wk    = (const float*)d_in[3];
    const float* bk    = (const float*)d_in[4];
    const float* Wv    = (const float*)d_in[5];
    const float* bv    = (const float*)d_in[6];
    const float* gamma = (const float*)d_in[7];
    float* out = (float*)d_out;

    proj_kernel<<<dim3(NPOS / 64, 5, BATCH), 256>>>(x, Wq, bq, Wk, bk, Wv, bv);

    cudaFuncSetAttribute(attn_kernel, cudaFuncAttributeMaxDynamicSharedMemorySize,
                         SMEM_BYTES);
    attn_kernel<<<dim3(NPOS / 128, BATCH), 512, SMEM_BYTES>>>(x, gamma, out);
}

// round 9
// speedup vs baseline: 1.8054x; 1.5138x over previous
#include <cuda_runtime.h>
#include <cuda_bf16.h>
#include <cstdint>

#define BATCH 8
#define NPOS 4096
#define CDIM 256

// Scratch: Q bf16 [b][n][32] (pre-scaled by log2e), K bf16 [b][n][32],
// V channel-major bf16 [b][c][n], x transposed bf16 [b][n][c].
__device__ __nv_bfloat16 g_q[(size_t)BATCH * NPOS * 32];
__device__ __nv_bfloat16 g_k[(size_t)BATCH * NPOS * 32];
__device__ __nv_bfloat16 g_v[(size_t)BATCH * CDIM * NPOS];
__device__ __nv_bfloat16 g_xb[(size_t)BATCH * NPOS * CDIM];

// ---------------- helpers ----------------
__device__ __forceinline__ uint32_t smem_u32(const void* p) {
    uint32_t a;
    asm("{ .reg .u64 t; cvta.to.shared.u64 t, %1; cvt.u32.u64 %0, t; }" : "=r"(a) : "l"(p));
    return a;
}
__device__ __forceinline__ float ex2f(float x) {
    float y; asm("ex2.approx.f32 %0, %1;" : "=f"(y) : "f"(x)); return y;
}
__device__ __forceinline__ void sts32(uint32_t a, uint32_t v) {
    asm volatile("st.shared.b32 [%0], %1;" :: "r"(a), "r"(v));
}
__device__ __forceinline__ void cp16(uint32_t dst, const void* src) {
    asm volatile("cp.async.cg.shared.global [%0], [%1], 16;" :: "r"(dst), "l"(src));
}
#define CP_COMMIT() asm volatile("cp.async.commit_group;" ::: "memory")
#define CP_WAIT(N)  asm volatile("cp.async.wait_group %0;" :: "n"(N) : "memory")

__device__ __forceinline__ void ldm_x4(uint32_t addr, uint32_t* r) {
    asm volatile("ldmatrix.sync.aligned.m8n8.x4.shared.b16 {%0,%1,%2,%3}, [%4];"
                 : "=r"(r[0]), "=r"(r[1]), "=r"(r[2]), "=r"(r[3]) : "r"(addr));
}
__device__ __forceinline__ void mma16816(float* c, const uint32_t* a, uint32_t b0, uint32_t b1) {
    asm volatile(
        "mma.sync.aligned.m16n8k16.row.col.f32.bf16.bf16.f32 "
        "{%0,%1,%2,%3}, {%4,%5,%6,%7}, {%8,%9}, {%0,%1,%2,%3};"
        : "+f"(c[0]), "+f"(c[1]), "+f"(c[2]), "+f"(c[3])
        : "r"(a[0]), "r"(a[1]), "r"(a[2]), "r"(a[3]), "r"(b0), "r"(b1));
}
__device__ __forceinline__ uint32_t bf2(float a, float b) {
    const __nv_bfloat162 t = __floats2bfloat162_rn(a, b);
    return *(const uint32_t*)&t;
}

#define LOG2E 1.4426950408889634f

// ================= Kernel 0: x fp32 [b][c][n] -> bf16 [b][n][c] =================
__global__ void __launch_bounds__(256) conv_kernel(const float* __restrict__ x)
{
    __shared__ float xs[64][68];
    const int b  = blockIdx.z;
    const int c0 = blockIdx.y * 64;
    const int n0 = blockIdx.x * 64;
    const int tid = threadIdx.x;

#pragma unroll
    for (int r = 0; r < 4; r++) {
        const int idx = tid + r * 256;
        const int cc = idx >> 4, nq = (idx & 15) * 4;
        *(float4*)&xs[cc][nq] =
            *(const float4*)(x + (((size_t)(b * CDIM + c0 + cc)) << 12) + n0 + nq);
    }
    __syncthreads();

    // thread: n = tid&63, jh = tid>>6 (two adjacent 8-c groups -> one 32B row segment)
    const int n = tid & 63, jh = tid >> 6;
    uint32_t p[8];
#pragma unroll
    for (int e = 0; e < 8; e++)
        p[e] = bf2(xs[jh * 16 + 2 * e][n], xs[jh * 16 + 2 * e + 1][n]);
    char* dst = (char*)g_xb + ((((size_t)b << 12) + n0 + n) << 9) + c0 * 2 + jh * 32;
    *(uint4*)dst        = make_uint4(p[0], p[1], p[2], p[3]);
    *(uint4*)(dst + 16) = make_uint4(p[4], p[5], p[6], p[7]);
}

// ================= Kernel A: projections on HMMA =================
// CTA: 64 o x 256 n, 256 threads (8 warps: 2 M x 4 N). K=256 in 8 chunks of 32.
// smem: W[64][264]bf16 @0 (33792B), xb 2x [256][40]bf16 @33792 (20480B each).
// Epilogue stage so[64][280]bf16 aliases base. Total 74752B.
#define PJ_W   0
#define PJ_X   33792
#define PJ_XSTR 20480
#define PROJ_SMEM 74752

__global__ void __launch_bounds__(256) proj_kernel(
    const float* __restrict__ Wq, const float* __restrict__ bq,
    const float* __restrict__ Wk, const float* __restrict__ bk,
    const float* __restrict__ Wv, const float* __restrict__ bv)
{
    extern __shared__ char psm[];
    const uint32_t sbp = smem_u32(psm);
    const int tid = threadIdx.x;
    const int w = tid >> 5, lane = tid & 31;
    const int lg = lane >> 2, ll = lane & 3;
    const int b  = blockIdx.z;
    const int oy = blockIdx.y;          // 0 = Q+K, 1..4 = V quarters
    const int n0 = blockIdx.x * 256;

    const int mo = (w & 1) * 32;        // warp M offset
    const int nb = (w >> 1) * 64;       // warp N offset

    const uint32_t a_off_w = (lane & 15) * 528 + ((lane >> 4) << 4);
    const uint32_t b_off_x = ((lane & 7) + ((lane >> 4) << 3)) * 80 + (((lane >> 3) & 1) << 4);

    // Stage W tile (64 rows x 256 c) fp32 -> bf16, rows stride 528B
    {
        const int ob = oy * 64;
#pragma unroll
        for (int r = 0; r < 8; r++) {
            const int idx = tid + r * 256;      // 2048 float2-groups? use 2 floats each
            const int row = idx >> 5;           // 64 rows
            const int cq  = (idx & 31) * 8;     // 8 floats
            const int og  = ob + row;
            const float* wrow;
            if (og < 32)      wrow = Wq + og * CDIM;
            else if (og < 64) wrow = Wk + (og - 32) * CDIM;
            else              wrow = Wv + (og - 64) * CDIM;
            const float4 v0 = *(const float4*)(wrow + cq);
            const float4 v1 = *(const float4*)(wrow + cq + 4);
            const uint32_t base = sbp + PJ_W + row * 528 + cq * 2;
            sts32(base + 0,  bf2(v0.x, v0.y));
            sts32(base + 4,  bf2(v0.z, v0.w));
            sts32(base + 8,  bf2(v1.x, v1.y));
            sts32(base + 12, bf2(v1.z, v1.w));
        }
    }

    const char* xbg = (const char*)g_xb + ((((size_t)b << 12) + n0) << 9);

#define PJ_LOAD(ci) do { \
    const uint32_t _d = sbp + PJ_X + ((ci) & 1) * PJ_XSTR; \
    _Pragma("unroll") \
    for (int _r = 0; _r < 4; _r++) { \
        const int _g = tid + _r * 256; \
        const int _n = _g >> 2, _p = _g & 3; \
        cp16(_d + _n * 80 + _p * 16, xbg + (size_t)_n * 512 + (ci) * 64 + _p * 16); \
    } CP_COMMIT(); } while (0)

    PJ_LOAD(0);

    float of[2][8][4];
#pragma unroll
    for (int mt = 0; mt < 2; mt++)
#pragma unroll
        for (int nf = 0; nf < 8; nf++)
#pragma unroll
            for (int r = 0; r < 4; r++) of[mt][nf][r] = 0.0f;

#pragma unroll 1
    for (int i = 0; i < 8; i++) {
        CP_WAIT(0);
        __syncthreads();
        if (i + 1 < 8) PJ_LOAD(i + 1);

        uint32_t afr[2][2][4];
#pragma unroll
        for (int mt = 0; mt < 2; mt++)
#pragma unroll
            for (int kk = 0; kk < 2; kk++)
                ldm_x4(sbp + PJ_W + (uint32_t)(mo + mt * 16) * 528 + a_off_w + i * 64 + kk * 32,
                       afr[mt][kk]);

        const uint32_t xbs = sbp + PJ_X + (i & 1) * PJ_XSTR;
#pragma unroll
        for (int np = 0; np < 4; np++) {
            uint32_t bfr[2][4];
            ldm_x4(xbs + (uint32_t)(nb + np * 16) * 80 + b_off_x + 0,  bfr[0]);
            ldm_x4(xbs + (uint32_t)(nb + np * 16) * 80 + b_off_x + 32, bfr[1]);
#pragma unroll
            for (int mt = 0; mt < 2; mt++)
#pragma unroll
                for (int nf2 = 0; nf2 < 2; nf2++) {
                    const int nf = np * 2 + nf2;
                    mma16816(of[mt][nf], afr[mt][0], bfr[0][nf2 * 2], bfr[0][nf2 * 2 + 1]);
                    mma16816(of[mt][nf], afr[mt][1], bfr[1][nf2 * 2], bfr[1][nf2 * 2 + 1]);
                }
        }
        __syncthreads();
    }

    // bias + stage so[o][n] bf16, stride 280 (560B)
    float bias[2][2];
#pragma unroll
    for (int mt = 0; mt < 2; mt++)
#pragma unroll
        for (int h = 0; h < 2; h++) {
            const int og = oy * 64 + mo + mt * 16 + h * 8 + lg;
            bias[mt][h] = (og < 32) ? bq[og] : (og < 64 ? bk[og - 32] : bv[og - 64]);
        }
    const float scl = (oy == 0 && mo == 0) ? LOG2E : 1.0f;

    __syncthreads();  // all ldmatrix reads of W/x done before aliasing smem
#pragma unroll
    for (int mt = 0; mt < 2; mt++)
#pragma unroll
        for (int nf = 0; nf < 8; nf++) {
            const int o0 = mo + mt * 16 + lg;
            const int n  = nb + nf * 8 + ll * 2;
            sts32(sbp + o0 * 560 + n * 2,
                  bf2((of[mt][nf][0] + bias[mt][0]) * scl, (of[mt][nf][1] + bias[mt][0]) * scl));
            sts32(sbp + (o0 + 8) * 560 + n * 2,
                  bf2((of[mt][nf][2] + bias[mt][1]) * scl, (of[mt][nf][3] + bias[mt][1]) * scl));
        }
    __syncthreads();

    if (oy == 0) {
        // Q (o 0..31) and K (o 32..63): emit rows [n][32] bf16 (64B)
        const int half = tid >> 7;          // 0 = Q, 1 = K
        const int t    = tid & 127;
        const int obase = half * 32;
        uint32_t val[32];
#pragma unroll
        for (int o = 0; o < 32; o++)
            val[o] = *(const uint32_t*)(psm + (obase + o) * 560 + t * 4);
        char* dst0 = (char*)((half ? g_k : g_q) + (((size_t)b << 12) + n0 + 2 * t) * 32);
#pragma unroll
        for (int rowp = 0; rowp < 2; rowp++) {
            const uint32_t sel = rowp ? 0x7632u : 0x5410u;
            uint32_t pk[16];
#pragma unroll
            for (int o2 = 0; o2 < 16; o2++)
                pk[o2] = __byte_perm(val[2 * o2], val[2 * o2 + 1], sel);
            char* dst = dst0 + rowp * 64;
#pragma unroll
            for (int q4 = 0; q4 < 4; q4++)
                *(uint4*)(dst + q4 * 16) =
                    make_uint4(pk[q4 * 4], pk[q4 * 4 + 1], pk[q4 * 4 + 2], pk[q4 * 4 + 3]);
        }
    } else {
        // V: rows c = (oy-1)*64 + o, contiguous 512B per row segment
#pragma unroll
        for (int r = 0; r < 8; r++) {
            const int idx = tid + r * 256;
            const int row = idx >> 5, q = idx & 31;
            const uint4 v = *(const uint4*)(psm + row * 560 + q * 16);
            char* dst = (char*)g_v +
                (((size_t)(b * CDIM + (oy - 1) * 64 + row)) << 13) + n0 * 2 + q * 16;
            *(uint4*)dst = v;
        }
    }
}

// ================= Kernel B: HMMA flash attention (R8, unchanged) =================
#define QS_OFF 0
#define KS_OFF 10240
#define K_STR  5120
#define PS_OFF 30720
#define P_STR  18432
#define RS_OFF 67584
#define VS_OFF 68608
#define V_STR  36864
#define SMEM_BYTES 216064

__global__ void __launch_bounds__(512, 1) attn_kernel(
    const float* __restrict__ x,
    const float* __restrict__ gamma,
    float* __restrict__ out)
{
    extern __shared__ char smc[];
    const uint32_t sb = smem_u32(smc);
    const int tid = threadIdx.x;
    const int w = tid >> 5, lane = tid & 31;
    const int lg = lane >> 2, ll = lane & 3;
    const int b = blockIdx.y, m0 = blockIdx.x * 128;

    const int s_mb = (w >> 1) * 16, s_nb = (w & 1) * 32;
    const int p_mb = (w >> 2) * 32, p_cb = (w & 3) * 64;

    const uint32_t a_off144 = (lane & 15) * 144 + ((lane >> 4) << 4);
    const uint32_t a_off80  = (lane & 15) * 80  + ((lane >> 4) << 4);
    const uint32_t b_off_v  = ((lane & 7) + ((lane >> 4) << 3)) * 144 + (((lane >> 3) & 1) << 4);
    const uint32_t b_off_k  = ((lane & 7) + ((lane >> 4) << 3)) * 80  + (((lane >> 3) & 1) << 4);

    const char* gq = (const char*)g_q + ((size_t)(b << 12) + m0) * 64;
    const char* gk = (const char*)g_k + ((size_t)b << 18);
    const char* gv = (const char*)g_v + (size_t)b * CDIM * 8192;

#define LOAD_KV(t2) do { \
    const int _sl = (t2) & 3; \
    if (tid < 256) \
        cp16(sb + KS_OFF + _sl * K_STR + (tid >> 2) * 80 + (tid & 3) * 16, \
             gk + (size_t)(t2) * 4096 + tid * 16); \
    _Pragma("unroll") \
    for (int _i = 0; _i < 4; _i++) { \
        const int _e = tid + _i * 512, _c = _e >> 3, _j = _e & 7; \
        cp16(sb + VS_OFF + _sl * V_STR + _c * 144 + _j * 16, \
             gv + (size_t)_c * 8192 + (size_t)(t2) * 128 + _j * 16); \
    } CP_COMMIT(); } while (0)

    cp16(sb + QS_OFF + (tid >> 2) * 80 + (tid & 3) * 16, gq + tid * 16);
    if (tid < 256)
        cp16(sb + KS_OFF + (tid >> 2) * 80 + (tid & 3) * 16, gk + tid * 16);
#pragma unroll
    for (int i = 0; i < 4; i++) {
        const int e = tid + i * 512, c = e >> 3, jj = e & 7;
        cp16(sb + VS_OFF + c * 144 + jj * 16, gv + (size_t)c * 8192 + jj * 16);
    }
    CP_COMMIT();
    LOAD_KV(1);
    CP_WAIT(0);
    __syncthreads();

    float of[2][8][4];
#pragma unroll
    for (int mt = 0; mt < 2; mt++)
#pragma unroll
        for (int nf = 0; nf < 8; nf++)
#pragma unroll
            for (int r = 0; r < 4; r++) of[mt][nf][r] = 0.0f;
    float rsA = 0.0f, rsB = 0.0f;

#define S_COMPUTE(TILE, sf) do { \
    const uint32_t kbt = sb + KS_OFF + ((TILE) & 3) * K_STR; \
    uint32_t bfr[2][2][4]; \
    _Pragma("unroll") \
    for (int ks = 0; ks < 2; ks++) \
        _Pragma("unroll") \
        for (int np = 0; np < 2; np++) \
            ldm_x4(kbt + (uint32_t)(s_nb + np * 16) * 80 + b_off_k + ks * 32, bfr[ks][np]); \
    _Pragma("unroll") \
    for (int ks = 0; ks < 2; ks++) { \
        uint32_t a[4]; \
        ldm_x4(sb + QS_OFF + (uint32_t)s_mb * 80 + a_off80 + ks * 32, a); \
        _Pragma("unroll") \
        for (int nf = 0; nf < 4; nf++) \
            mma16816(sf[nf], a, bfr[ks][nf >> 1][(nf & 1) * 2], \
                     bfr[ks][nf >> 1][(nf & 1) * 2 + 1]); \
    } } while (0)

#define SOFTMAX_Q(TILE, NF, sf) do { \
    const float p0 = ex2f(sf[NF][0]), p1 = ex2f(sf[NF][1]); \
    const float p2 = ex2f(sf[NF][2]), p3 = ex2f(sf[NF][3]); \
    const __nv_bfloat162 t01 = __floats2bfloat162_rn(p0, p1); \
    const __nv_bfloat162 t23 = __floats2bfloat162_rn(p2, p3); \
    const float2 f01 = __bfloat1622float2(t01); \
    const float2 f23 = __bfloat1622float2(t23); \
    rsA += f01.x + f01.y; \
    rsB += f23.x + f23.y; \
    const uint32_t pr0 = sb + PS_OFF + ((TILE) & 1) * P_STR + (s_mb + lg) * 144; \
    const int nb2 = (s_nb + (NF) * 8 + ll * 2) * 2; \
    sts32(pr0 + nb2, *(const uint32_t*)&t01); \
    sts32(pr0 + 8 * 144 + nb2, *(const uint32_t*)&t23); } while (0)

    {
        float sf[4][4];
#pragma unroll
        for (int nf = 0; nf < 4; nf++)
#pragma unroll
            for (int r = 0; r < 4; r++) sf[nf][r] = 0.0f;
        S_COMPUTE(0, sf);
#pragma unroll
        for (int nf = 0; nf < 4; nf++) SOFTMAX_Q(0, nf, sf);
    }

    for (int kt = 0; kt < 64; kt++) {
        if (kt + 2 < 64) LOAD_KV(kt + 2);
        if (kt < 62) { CP_WAIT(1); } else { CP_WAIT(0); }
        __syncthreads();

        const bool doS = (kt < 63);
        float sf[4][4];
#pragma unroll
        for (int nf = 0; nf < 4; nf++)
#pragma unroll
            for (int r = 0; r < 4; r++) sf[nf][r] = 0.0f;
        if (doS) S_COMPUTE(kt + 1, sf);

        const uint32_t pt = sb + PS_OFF + (kt & 1) * P_STR;
        const uint32_t vt = sb + VS_OFF + (kt & 3) * V_STR;
#pragma unroll
        for (int ks = 0; ks < 4; ks++) {
            const int kb = ks * 32;
            uint32_t pa[2][4];
            ldm_x4(pt + (uint32_t)p_mb * 144 + a_off144 + kb, pa[0]);
            ldm_x4(pt + (uint32_t)(p_mb + 16) * 144 + a_off144 + kb, pa[1]);
            uint32_t vb[4][4];
#pragma unroll
            for (int np = 0; np < 4; np++)
                ldm_x4(vt + (uint32_t)(p_cb + np * 16) * 144 + b_off_v + kb, vb[np]);
#pragma unroll
            for (int nf = 0; nf < 8; nf++) {
                const uint32_t b0 = vb[nf >> 1][(nf & 1) * 2];
                const uint32_t b1 = vb[nf >> 1][(nf & 1) * 2 + 1];
                mma16816(of[0][nf], pa[0], b0, b1);
                mma16816(of[1][nf], pa[1], b0, b1);
            }
            if (doS) SOFTMAX_Q(kt + 1, ks, sf);
        }
    }

    rsA += __shfl_xor_sync(0xffffffffu, rsA, 1);
    rsA += __shfl_xor_sync(0xffffffffu, rsA, 2);
    rsB += __shfl_xor_sync(0xffffffffu, rsB, 1);
    rsB += __shfl_xor_sync(0xffffffffu, rsB, 2);
    float* rowarr = (float*)(smc + RS_OFF);
    if (ll == 0) {
        rowarr[(s_mb + lg) * 2 + (w & 1)] = rsA;
        rowarr[(s_mb + 8 + lg) * 2 + (w & 1)] = rsB;
    }
    __syncthreads();

    const float gm = gamma[0];
    float inv[4];
#pragma unroll
    for (int mt = 0; mt < 2; mt++)
#pragma unroll
        for (int h = 0; h < 2; h++) {
            const int r = p_mb + mt * 16 + h * 8 + lg;
            inv[mt * 2 + h] = gm / (rowarr[2 * r] + rowarr[2 * r + 1]);
        }

    float* ost = (float*)(smc + VS_OFF);
#pragma unroll 1
    for (int chunk = 0; chunk < 2; chunk++) {
        if (((w & 3) >> 1) == chunk) {
#pragma unroll
            for (int mt = 0; mt < 2; mt++)
#pragma unroll
                for (int nf = 0; nf < 8; nf++) {
                    const int cl = (p_cb - chunk * 128) + nf * 8 + ll * 2;
                    const int m = p_mb + mt * 16 + lg;
                    ost[cl * 132 + m]           = of[mt][nf][0] * inv[mt * 2];
                    ost[(cl + 1) * 132 + m]     = of[mt][nf][1] * inv[mt * 2];
                    ost[cl * 132 + m + 8]       = of[mt][nf][2] * inv[mt * 2 + 1];
                    ost[(cl + 1) * 132 + m + 8] = of[mt][nf][3] * inv[mt * 2 + 1];
                }
        }
        __syncthreads();
        const int m = tid & 127, cb = tid >> 7;
#pragma unroll 4
        for (int cc = 0; cc < 32; cc++) {
            const int cl = cc * 4 + cb;
            const int c = chunk * 128 + cl;
            const size_t off = ((size_t)b * CDIM + c) * NPOS + m0 + m;
            out[off] = ost[cl * 132 + m] + x[off];
        }
        __syncthreads();
    }
}

// ================= launch =================
extern "C" void kernel_launch(void* const* d_in, const int* in_sizes, int n_in,
                              void* d_out, int out_size)
{
    const float* x     = (const float*)d_in[0];
    const float* Wq    = (const float*)d_in[1];
    const float* bq    = (const float*)d_in[2];
    const float* Wk    = (const float*)d_in[3];
    const float* bk    = (const float*)d_in[4];
    const float* Wv    = (const float*)d_in[5];
    const float* bv    = (const float*)d_in[6];
    const float* gamma = (const float*)d_in[7];
    float* out = (float*)d_out;

    conv_kernel<<<dim3(NPOS / 64, CDIM / 64, BATCH), 256>>>(x);

    cudaFuncSetAttribute(proj_kernel, cudaFuncAttributeMaxDynamicSharedMemorySize,
                         PROJ_SMEM);
    proj_kernel<<<dim3(NPOS / 256, 5, BATCH), 256, PROJ_SMEM>>>(Wq, bq, Wk, bk, Wv, bv);

    cudaFuncSetAttribute(attn_kernel, cudaFuncAttributeMaxDynamicSharedMemorySize,
                         SMEM_BYTES);
    attn_kernel<<<dim3(NPOS / 128, BATCH), 512, SMEM_BYTES>>>(x, gamma, out);
}